// round 3
// baseline (speedup 1.0000x reference)
#include <cuda_runtime.h>
#include <cuda_fp16.h>
#include <cstdint>

// Problem constants
#define BB 2
#define CC 256
#define HH 64
#define WW 64
#define HWC (HH*WW)          // 4096
#define NQ (BB*HWC)          // 8192
#define NLVL 4
#define RAD 4
#define QT 16                // queries per tile
#define PAD 16               // pyramid guard border (flow bounded by +-10, taps +-5)

// Padded level widths: (64>>l) + 2*PAD
#define WP0 96
#define WP1 64
#define WP2 48
#define WP3 40

// Scratch (device globals; allocation-free rule)
__device__ float  g_f1t[BB*HWC*CC];              // (B, HW, C) fp32, 8 MB
__device__ __half g_f2p0[BB*WP0*WP0*CC];         // 9.4 MB (zero-padded)
__device__ __half g_f2p1[BB*WP1*WP1*CC];         // 4.2 MB
__device__ __half g_f2p2[BB*WP2*WP2*CC];         // 2.4 MB
__device__ __half g_f2p3[BB*WP3*WP3*CC];         // 1.6 MB

__device__ __forceinline__ __half* level_ptr(int l) {
    switch (l) {
        case 0: return g_f2p0;
        case 1: return g_f2p1;
        case 2: return g_f2p2;
        default: return g_f2p3;
    }
}

// ---------------------------------------------------------------------------
// Zero-fill all padded pyramid buffers (uint4 = 8 halfs per thread)
// ---------------------------------------------------------------------------
#define N0U4 (BB*WP0*WP0*CC/8)
#define N1U4 (BB*WP1*WP1*CC/8)
#define N2U4 (BB*WP2*WP2*CC/8)
#define N3U4 (BB*WP3*WP3*CC/8)
#define NTOTU4 (N0U4+N1U4+N2U4+N3U4)

__global__ void fill_zero_kernel() {
    int i = blockIdx.x * blockDim.x + threadIdx.x;
    if (i >= NTOTU4) return;
    uint4 z = make_uint4(0u, 0u, 0u, 0u);
    if (i < N0U4)                   { ((uint4*)g_f2p0)[i] = z; return; }
    i -= N0U4;
    if (i < N1U4)                   { ((uint4*)g_f2p1)[i] = z; return; }
    i -= N1U4;
    if (i < N2U4)                   { ((uint4*)g_f2p2)[i] = z; return; }
    i -= N2U4;
    ((uint4*)g_f2p3)[i] = z;
}

// ---------------------------------------------------------------------------
// Transpose fmap1 (B,C,HW) -> (B,HW,C) fp32
// ---------------------------------------------------------------------------
__global__ void transpose_f1_kernel(const float* __restrict__ in) {
    __shared__ float tile[32][33];
    int b   = blockIdx.z;
    int hw0 = blockIdx.x * 32;
    int c0  = blockIdx.y * 32;
    int tx = threadIdx.x, ty = threadIdx.y;   // block (32, 8)
#pragma unroll
    for (int i = 0; i < 32; i += 8)
        tile[ty + i][tx] = in[(b*CC + c0 + ty + i) * HWC + hw0 + tx];
    __syncthreads();
#pragma unroll
    for (int i = 0; i < 32; i += 8)
        g_f1t[(b*HWC + hw0 + ty + i) * CC + c0 + tx] = tile[tx][ty + i];
}

// Transpose fmap2 (B,C,HW) -> padded fp16 pyramid level 0
__global__ void transpose_f2_kernel(const float* __restrict__ in) {
    __shared__ float tile[32][33];
    int b   = blockIdx.z;
    int hw0 = blockIdx.x * 32;
    int c0  = blockIdx.y * 32;
    int tx = threadIdx.x, ty = threadIdx.y;
#pragma unroll
    for (int i = 0; i < 32; i += 8)
        tile[ty + i][tx] = in[(b*CC + c0 + ty + i) * HWC + hw0 + tx];
    __syncthreads();
#pragma unroll
    for (int i = 0; i < 32; i += 8) {
        int hw = hw0 + ty + i;
        int y = hw >> 6, x = hw & 63;
        g_f2p0[(((size_t)b*WP0 + y + PAD)*WP0 + x + PAD)*CC + c0 + tx] =
            __float2half_rn(tile[tx][ty + i]);
    }
}

// ---------------------------------------------------------------------------
// 2x2 mean pool: padded level l -> padded level l+1 (interiors only)
// ---------------------------------------------------------------------------
__global__ void pool_kernel(int lin) {
    const __half2* in  = (const __half2*)level_ptr(lin);
    __half2*       out = (__half2*)level_ptr(lin + 1);
    int Wi = 64 >> lin;
    int Pi = Wi + 2*PAD;
    int Wo = Wi >> 1;
    int Po = Wo + 2*PAD;
    int total = BB * Wo * Wo * (CC / 2);
    int idx = blockIdx.x * blockDim.x + threadIdx.x;
    if (idx >= total) return;
    int c2 = idx & (CC/2 - 1);
    int j  = (idx >> 7) % (Wo * Wo);
    int b  = idx / ((CC/2) * Wo * Wo);
    int Y = j / Wo, X = j % Wo;
    const __half2* base = in + ((size_t)b * Pi * Pi + (size_t)PAD * Pi + PAD) * (CC/2);
    float2 a  = __half22float2(base[((size_t)(2*Y    )*Pi + 2*X    ) * (CC/2) + c2]);
    float2 bb = __half22float2(base[((size_t)(2*Y    )*Pi + 2*X + 1) * (CC/2) + c2]);
    float2 c  = __half22float2(base[((size_t)(2*Y + 1)*Pi + 2*X    ) * (CC/2) + c2]);
    float2 d  = __half22float2(base[((size_t)(2*Y + 1)*Pi + 2*X + 1) * (CC/2) + c2]);
    out[((size_t)b * Po * Po + (size_t)(Y + PAD) * Po + X + PAD) * (CC/2) + c2] =
        __floats2half2_rn(0.25f * (a.x + bb.x + c.x + d.x),
                          0.25f * (a.y + bb.y + c.y + d.y));
}

// ---------------------------------------------------------------------------
// Sampling kernel: grid = (512 tiles, 4 levels), block 256.
// Unconditional loads (zero-padded pyramid), 2 acc chains, 5-tap unroll.
// ---------------------------------------------------------------------------
__global__ __launch_bounds__(256)
void corr_sample_kernel(const float* __restrict__ coords,
                        float* __restrict__ out) {
    __shared__ float sT[QT][110];        // [q][ty*11 + tx]
    __shared__ float sX[QT], sY[QT];

    int l    = blockIdx.y;
    int bidx = blockIdx.x;               // 0..511
    int b    = bidx >> 8;
    int hw0  = (bidx & 255) * QT;
    int tid  = threadIdx.x;
    int sub  = tid & 7;                  // lane within 8-lane group
    int grp  = tid >> 3;                 // 0..31
    int q    = grp >> 1;                 // query 0..15
    int half = grp & 1;

    if (tid < QT) {
        sX[tid] = coords[(b*2 + 0) * HWC + hw0 + tid];
        sY[tid] = coords[(b*2 + 1) * HWC + hw0 + tid];
    }

    // This thread's 32 f1 channels of its query
    float rf1[32];
    {
        int n = b * HWC + hw0 + q;
        const float4* f1v = (const float4*)(g_f1t + (size_t)n * CC + sub * 32);
#pragma unroll
        for (int u = 0; u < 8; u++) {
            float4 v = f1v[u];
            rf1[u*4+0] = v.x; rf1[u*4+1] = v.y;
            rf1[u*4+2] = v.z; rf1[u*4+3] = v.w;
        }
    }
    __syncthreads();

    int   Wl    = 64 >> l;
    int   Wp    = Wl + 2*PAD;
    float scale = 1.0f / (float)(1 << l);
    float xc = sX[q] * scale, yc = sY[q] * scale;
    int   bx = (int)floorf(xc) - RAD;
    int   by = (int)floorf(yc) - RAD;

    // lane base pointer at tap (0,0), pad offset folded in
    const __half* f2lane = level_ptr(l)
        + ((size_t)b * Wp * Wp + (size_t)(by + PAD) * Wp + (bx + PAD)) * CC
        + sub * 32;

    for (int ty = 0; ty < 10; ty++) {
        const __half* rowp = f2lane + (size_t)ty * Wp * CC + half * CC;
#pragma unroll
        for (int k = 0; k < 5; k++) {
            const uint4* p = (const uint4*)(rowp + (size_t)(2*k) * CC);
            uint4 h0 = p[0], h1 = p[1], h2 = p[2], h3 = p[3];
            float acc0 = 0.f, acc1 = 0.f;
            float2 f;
            f = __half22float2(*(const __half2*)&h0.x);
            acc0 = fmaf(rf1[ 0], f.x, acc0); acc0 = fmaf(rf1[ 1], f.y, acc0);
            f = __half22float2(*(const __half2*)&h0.y);
            acc0 = fmaf(rf1[ 2], f.x, acc0); acc0 = fmaf(rf1[ 3], f.y, acc0);
            f = __half22float2(*(const __half2*)&h0.z);
            acc0 = fmaf(rf1[ 4], f.x, acc0); acc0 = fmaf(rf1[ 5], f.y, acc0);
            f = __half22float2(*(const __half2*)&h0.w);
            acc0 = fmaf(rf1[ 6], f.x, acc0); acc0 = fmaf(rf1[ 7], f.y, acc0);
            f = __half22float2(*(const __half2*)&h1.x);
            acc1 = fmaf(rf1[ 8], f.x, acc1); acc1 = fmaf(rf1[ 9], f.y, acc1);
            f = __half22float2(*(const __half2*)&h1.y);
            acc1 = fmaf(rf1[10], f.x, acc1); acc1 = fmaf(rf1[11], f.y, acc1);
            f = __half22float2(*(const __half2*)&h1.z);
            acc1 = fmaf(rf1[12], f.x, acc1); acc1 = fmaf(rf1[13], f.y, acc1);
            f = __half22float2(*(const __half2*)&h1.w);
            acc1 = fmaf(rf1[14], f.x, acc1); acc1 = fmaf(rf1[15], f.y, acc1);
            f = __half22float2(*(const __half2*)&h2.x);
            acc0 = fmaf(rf1[16], f.x, acc0); acc0 = fmaf(rf1[17], f.y, acc0);
            f = __half22float2(*(const __half2*)&h2.y);
            acc0 = fmaf(rf1[18], f.x, acc0); acc0 = fmaf(rf1[19], f.y, acc0);
            f = __half22float2(*(const __half2*)&h2.z);
            acc0 = fmaf(rf1[20], f.x, acc0); acc0 = fmaf(rf1[21], f.y, acc0);
            f = __half22float2(*(const __half2*)&h2.w);
            acc0 = fmaf(rf1[22], f.x, acc0); acc0 = fmaf(rf1[23], f.y, acc0);
            f = __half22float2(*(const __half2*)&h3.x);
            acc1 = fmaf(rf1[24], f.x, acc1); acc1 = fmaf(rf1[25], f.y, acc1);
            f = __half22float2(*(const __half2*)&h3.y);
            acc1 = fmaf(rf1[26], f.x, acc1); acc1 = fmaf(rf1[27], f.y, acc1);
            f = __half22float2(*(const __half2*)&h3.z);
            acc1 = fmaf(rf1[28], f.x, acc1); acc1 = fmaf(rf1[29], f.y, acc1);
            f = __half22float2(*(const __half2*)&h3.w);
            acc1 = fmaf(rf1[30], f.x, acc1); acc1 = fmaf(rf1[31], f.y, acc1);

            float acc = acc0 + acc1;
            acc += __shfl_down_sync(0xffffffffu, acc, 4);
            acc += __shfl_down_sync(0xffffffffu, acc, 2);
            acc += __shfl_down_sync(0xffffffffu, acc, 1);
            if (sub == 0) sT[q][ty * 11 + half + 2*k] = acc * 0.0625f; // 1/sqrt(C)
        }
    }
    __syncthreads();

    // 81 outputs x 16 queries, lane -> query for coalesced stores
#pragma unroll
    for (int it = 0; it < 6; it++) {
        int idx = tid + it * 256;
        if (idx < 81 * QT) {
            int k  = idx >> 4;           // output tap 0..80
            int qq = idx & 15;
            int cx = k / 9;              // x-offset index (ref adds dy-grid to x)
            int ry = k % 9;              // y-offset index
            float xq2 = sX[qq] * scale;
            float yq2 = sY[qq] * scale;
            float fx = xq2 - floorf(xq2);
            float fy = yq2 - floorf(yq2);
            float v00 = sT[qq][ ry      * 11 + cx    ];
            float v01 = sT[qq][ ry      * 11 + cx + 1];
            float v10 = sT[qq][(ry + 1) * 11 + cx    ];
            float v11 = sT[qq][(ry + 1) * 11 + cx + 1];
            float v = (1.f - fy) * ((1.f - fx) * v00 + fx * v01)
                    +        fy  * ((1.f - fx) * v10 + fx * v11);
            out[((size_t)(b * 324 + l * 81 + k)) * HWC + hw0 + qq] = v;
        }
    }
}

// ---------------------------------------------------------------------------
extern "C" void kernel_launch(void* const* d_in, const int* in_sizes, int n_in,
                              void* d_out, int out_size) {
    const float* fmap1  = (const float*)d_in[0];
    const float* fmap2  = (const float*)d_in[1];
    const float* coords = (const float*)d_in[2];
    float* out = (float*)d_out;

    fill_zero_kernel<<<(NTOTU4 + 255) / 256, 256>>>();

    dim3 tgrid(HWC / 32, CC / 32, BB);   // (128, 8, 2)
    dim3 tblk(32, 8);
    transpose_f1_kernel<<<tgrid, tblk>>>(fmap1);
    transpose_f2_kernel<<<tgrid, tblk>>>(fmap2);

    {
        int t1 = BB * 32 * 32 * (CC/2);
        int t2 = BB * 16 * 16 * (CC/2);
        int t3 = BB * 8  * 8  * (CC/2);
        pool_kernel<<<(t1 + 255) / 256, 256>>>(0);
        pool_kernel<<<(t2 + 255) / 256, 256>>>(1);
        pool_kernel<<<(t3 + 255) / 256, 256>>>(2);
    }

    dim3 sgrid(NQ / QT, NLVL);           // (512, 4)
    corr_sample_kernel<<<sgrid, 256>>>(coords, out);
}

// round 5
// speedup vs baseline: 1.3331x; 1.3331x over previous
#include <cuda_runtime.h>
#include <cuda_fp16.h>
#include <cstdint>

// Problem constants
#define BB 2
#define CC 256
#define HH 64
#define WW 64
#define HWC (HH*WW)          // 4096
#define NQ (BB*HWC)          // 8192
#define NLVL 4
#define RAD 4
#define QT 16                // queries per sampler tile

// GEMM tiling
#define TM 128
#define TN 128
#define GEMM_SMEM_BYTES (TM*CC*2 + TN*CC*2 + 1024)   // A + B + align slack

// Scratch (device globals; allocation-free rule)
__device__ __half g_f1h[BB*HWC*CC];          // (B, HW, C) fp16, 4 MB
__device__ __half g_f2h[BB*HWC*CC];          // (B, HW, C) fp16, 4 MB
__device__ __half g_c0[(size_t)NQ*64*64];    // corr lvl0, 67 MB
__device__ __half g_c1[(size_t)NQ*32*32];    // 16.8 MB
__device__ __half g_c2[(size_t)NQ*16*16];    // 4.2 MB
__device__ __half g_c3[(size_t)NQ*8*8];      // 1.05 MB

__device__ __forceinline__ __half* clevel_ptr(int l) {
    switch (l) {
        case 0: return g_c0;
        case 1: return g_c1;
        case 2: return g_c2;
        default: return g_c3;
    }
}

__device__ __forceinline__ uint32_t smem_u32(const void* p) {
    uint32_t a;
    asm("{ .reg .u64 t; cvta.to.shared.u64 t, %1; cvt.u32.u64 %0, t; }"
        : "=r"(a) : "l"(p));
    return a;
}

// ---------------------------------------------------------------------------
// Transpose (B,C,HW) fp32 -> (B,HW,C) fp16
// ---------------------------------------------------------------------------
__global__ void transpose_f1_kernel(const float* __restrict__ in) {
    __shared__ float tile[32][33];
    int b = blockIdx.z, hw0 = blockIdx.x*32, c0 = blockIdx.y*32;
    int tx = threadIdx.x, ty = threadIdx.y;
#pragma unroll
    for (int i = 0; i < 32; i += 8)
        tile[ty + i][tx] = in[(b*CC + c0 + ty + i) * HWC + hw0 + tx];
    __syncthreads();
#pragma unroll
    for (int i = 0; i < 32; i += 8)
        g_f1h[((size_t)b*HWC + hw0 + ty + i) * CC + c0 + tx] =
            __float2half_rn(tile[tx][ty + i]);
}
__global__ void transpose_f2_kernel(const float* __restrict__ in) {
    __shared__ float tile[32][33];
    int b = blockIdx.z, hw0 = blockIdx.x*32, c0 = blockIdx.y*32;
    int tx = threadIdx.x, ty = threadIdx.y;
#pragma unroll
    for (int i = 0; i < 32; i += 8)
        tile[ty + i][tx] = in[(b*CC + c0 + ty + i) * HWC + hw0 + tx];
    __syncthreads();
#pragma unroll
    for (int i = 0; i < 32; i += 8)
        g_f2h[((size_t)b*HWC + hw0 + ty + i) * CC + c0 + tx] =
            __float2half_rn(tile[tx][ty + i]);
}

// ---------------------------------------------------------------------------
// GEMM via mma.sync (m16n8k16 f16->f32): corr = f1 @ f2^T / 16, fp16 out.
// Tile 128x128, K=256 fully resident in smem. 8 warps: warp (wm, wn) computes
// a 32(M) x 64(N) subtile. XOR-swizzled smem for conflict-free ldmatrix.
// ---------------------------------------------------------------------------
__global__ __launch_bounds__(256)
void gemm_kernel() {
    extern __shared__ __align__(16) char dsm[];
    uint32_t raw = smem_u32(dsm);
    uint32_t sb  = (raw + 1023u) & ~1023u;
    uint32_t sA  = sb;
    uint32_t sB  = sb + TM * CC * 2;
    char*    smp = dsm + (sb - raw);          // C++ pointer to same base

    int tid = threadIdx.x;
    int lid = tid & 31;
    int w   = tid >> 5;
    int wm  = w & 3;                          // M group (4 x 32)
    int wn  = w >> 2;                         // N group (2 x 64)
    int b   = blockIdx.z;
    int i0  = blockIdx.y * TM;
    int j0  = blockIdx.x * TN;

    // ---- global -> swizzled smem (A and B tiles, 64 KB each) ----
    {
        const uint4* gA = (const uint4*)(g_f1h + ((size_t)(b*HWC + i0)) * CC);
        const uint4* gB = (const uint4*)(g_f2h + ((size_t)(b*HWC + j0)) * CC);
#pragma unroll
        for (int it = 0; it < 16; it++) {
            int idx = tid + it * 256;         // 4096 uint4 per tile
            int r = idx >> 5, c = idx & 31;   // row, 16B-chunk
            uint32_t off = (uint32_t)r * 512u + (uint32_t)((c ^ (r & 7)) << 4);
            *(uint4*)(smp + off)              = gA[idx];
            *(uint4*)(smp + TM*CC*2 + off)    = gB[idx];
        }
    }
    __syncthreads();

    float acc[2][8][4];
#pragma unroll
    for (int mi = 0; mi < 2; mi++)
#pragma unroll
        for (int j = 0; j < 8; j++)
#pragma unroll
            for (int u = 0; u < 4; u++) acc[mi][j][u] = 0.f;

    int m0 = wm * 32;
    int nb = wn * 64;
    int arow = m0 + (lid & 15);               // + mi*16
    int acb  = lid >> 4;                      // A k-chunk bit
    int brow = nb + (lid & 7) + ((lid >> 4) << 3);   // + ng*16
    int bcb  = (lid >> 3) & 1;                // B k-chunk bit

#pragma unroll 4
    for (int ks = 0; ks < 16; ks++) {
        uint32_t a[2][4];
#pragma unroll
        for (int mi = 0; mi < 2; mi++) {
            int row = arow + mi * 16;
            int ch  = ks * 2 + acb;
            uint32_t addr = sA + (uint32_t)row * 512u
                          + (uint32_t)((ch ^ (row & 7)) << 4);
            asm volatile(
                "ldmatrix.sync.aligned.m8n8.x4.shared.b16 {%0,%1,%2,%3}, [%4];"
                : "=r"(a[mi][0]), "=r"(a[mi][1]), "=r"(a[mi][2]), "=r"(a[mi][3])
                : "r"(addr));
        }
        uint32_t bf[4][4];
#pragma unroll
        for (int ng = 0; ng < 4; ng++) {
            int row = brow + ng * 16;
            int ch  = ks * 2 + bcb;
            uint32_t addr = sB + (uint32_t)row * 512u
                          + (uint32_t)((ch ^ (row & 7)) << 4);
            asm volatile(
                "ldmatrix.sync.aligned.m8n8.x4.shared.b16 {%0,%1,%2,%3}, [%4];"
                : "=r"(bf[ng][0]), "=r"(bf[ng][1]), "=r"(bf[ng][2]), "=r"(bf[ng][3])
                : "r"(addr));
        }
#pragma unroll
        for (int mi = 0; mi < 2; mi++)
#pragma unroll
            for (int j = 0; j < 8; j++) {
                int ng = j >> 1, pr = (j & 1) * 2;
                asm volatile(
                    "mma.sync.aligned.m16n8k16.row.col.f32.f16.f16.f32 "
                    "{%0,%1,%2,%3}, {%4,%5,%6,%7}, {%8,%9}, {%0,%1,%2,%3};"
                    : "+f"(acc[mi][j][0]), "+f"(acc[mi][j][1]),
                      "+f"(acc[mi][j][2]), "+f"(acc[mi][j][3])
                    : "r"(a[mi][0]), "r"(a[mi][1]), "r"(a[mi][2]), "r"(a[mi][3]),
                      "r"(bf[ng][pr]), "r"(bf[ng][pr + 1]));
            }
    }
    __syncthreads();                          // done reading A/B smem

    // ---- epilogue: fragments -> smem (fp16, pitch 128) -> coalesced global ----
    {
        __half* epi = (__half*)smp;           // reuse A region (32 KB)
        const float s = 0.0625f;              // 1/sqrt(256)
#pragma unroll
        for (int mi = 0; mi < 2; mi++)
#pragma unroll
            for (int j = 0; j < 8; j++) {
                int n = nb + j * 8 + (lid & 3) * 2;
                int m = m0 + mi * 16 + (lid >> 2);
                *(__half2*)(epi + m * 128 + n) =
                    __floats2half2_rn(acc[mi][j][0] * s, acc[mi][j][1] * s);
                *(__half2*)(epi + (m + 8) * 128 + n) =
                    __floats2half2_rn(acc[mi][j][2] * s, acc[mi][j][3] * s);
            }
        __syncthreads();
        const uint4* ev = (const uint4*)epi;  // 16 uint4 per row
#pragma unroll
        for (int it = 0; it < 8; it++) {
            int idx = tid + it * 256;         // 2048 uint4
            int r = idx >> 4, c = idx & 15;
            *(uint4*)(g_c0 + ((size_t)(b*HWC + i0 + r)) * HWC + j0 + c * 8) =
                ev[idx];
        }
    }
}

// ---------------------------------------------------------------------------
// 2x2 mean pool on corr volumes: level lin -> lin+1 (fp16)
// ---------------------------------------------------------------------------
__global__ void cpool_kernel(int lin, int total) {
    int idx = blockIdx.x * blockDim.x + threadIdx.x;
    if (idx >= total) return;
    const __half2* in = (const __half2*)clevel_ptr(lin);
    __half* outp = clevel_ptr(lin + 1);
    int Wi = 64 >> lin;
    int Wo = Wi >> 1;
    int X = idx % Wo;
    int Y = (idx / Wo) % Wo;
    int n = idx / (Wo * Wo);
    __half2 a = in[((size_t)n * Wi + 2*Y    ) * (Wi/2) + X];
    __half2 b = in[((size_t)n * Wi + 2*Y + 1) * (Wi/2) + X];
    float2 fa = __half22float2(a);
    float2 fb = __half22float2(b);
    outp[idx] = __float2half_rn(0.25f * (fa.x + fa.y + fb.x + fb.y));
}

// ---------------------------------------------------------------------------
// Sampler: 16 queries per block (256 threads). Stage 4-level 10x10 windows
// in shared, then 324 bilinear outputs per query, coalesced stores.
// ---------------------------------------------------------------------------
__global__ __launch_bounds__(256)
void sample_kernel(const float* __restrict__ coords,
                   float* __restrict__ out) {
    __shared__ float sW[QT * 400];       // [q][l*100 + ty*10 + tx]
    __shared__ float sX[QT], sY[QT];

    int bidx = blockIdx.x;               // 0..511
    int b    = bidx >> 8;
    int hw0  = (bidx & 255) * QT;
    int tid  = threadIdx.x;

    if (tid < QT) {
        sX[tid] = coords[(b*2 + 0) * HWC + hw0 + tid];
        sY[tid] = coords[(b*2 + 1) * HWC + hw0 + tid];
    }
    __syncthreads();

    // 16 queries x 4 levels x 100 cells = 6400 taps
#pragma unroll
    for (int i = 0; i < 25; i++) {
        int idx = tid + i * 256;
        int q = idx / 400;
        int r = idx - q * 400;
        int l = r / 100;
        int t = r - l * 100;
        int Wl = 64 >> l;
        float scale = 1.0f / (float)(1 << l);
        float xc = sX[q] * scale, yc = sY[q] * scale;
        int bx = (int)floorf(xc) - RAD;
        int by = (int)floorf(yc) - RAD;
        int ix = bx + t % 10;
        int iy = by + t / 10;
        float v = 0.f;
        if (ix >= 0 && ix < Wl && iy >= 0 && iy < Wl) {
            const __half* cl = clevel_ptr(l);
            int n = b * HWC + hw0 + q;
            v = __half2float(cl[(size_t)n * Wl * Wl + iy * Wl + ix]);
        }
        sW[idx] = v;
    }
    __syncthreads();

    // 324 outputs x 16 queries = 5184
#pragma unroll
    for (int i = 0; i < 21; i++) {
        int idx = tid + i * 256;
        if (idx < 324 * QT) {
            int k  = idx >> 4;           // 0..323
            int qq = idx & 15;
            int l  = k / 81;
            int kk = k - l * 81;
            int cx = kk / 9;             // x-offset index (ref adds dy-grid to x)
            int ry = kk - cx * 9;        // y-offset index
            float scale = 1.0f / (float)(1 << l);
            float xq = sX[qq] * scale;
            float yq = sY[qq] * scale;
            float fx = xq - floorf(xq);
            float fy = yq - floorf(yq);
            const float* W = sW + qq * 400 + l * 100;
            float v00 = W[ ry      * 10 + cx    ];
            float v01 = W[ ry      * 10 + cx + 1];
            float v10 = W[(ry + 1) * 10 + cx    ];
            float v11 = W[(ry + 1) * 10 + cx + 1];
            float v = (1.f - fy) * ((1.f - fx) * v00 + fx * v01)
                    +        fy  * ((1.f - fx) * v10 + fx * v11);
            out[((size_t)(b * 324 + k)) * HWC + hw0 + qq] = v;
        }
    }
}

// ---------------------------------------------------------------------------
extern "C" void kernel_launch(void* const* d_in, const int* in_sizes, int n_in,
                              void* d_out, int out_size) {
    const float* fmap1  = (const float*)d_in[0];
    const float* fmap2  = (const float*)d_in[1];
    const float* coords = (const float*)d_in[2];
    float* out = (float*)d_out;

    cudaFuncSetAttribute(gemm_kernel,
                         cudaFuncAttributeMaxDynamicSharedMemorySize,
                         GEMM_SMEM_BYTES);

    dim3 tgrid(HWC / 32, CC / 32, BB);
    dim3 tblk(32, 8);
    transpose_f1_kernel<<<tgrid, tblk>>>(fmap1);
    transpose_f2_kernel<<<tgrid, tblk>>>(fmap2);

    dim3 ggrid(HWC / TN, HWC / TM, BB);  // (32, 32, 2)
    gemm_kernel<<<ggrid, 256, GEMM_SMEM_BYTES>>>();

    {
        int t1 = NQ * 32 * 32;
        int t2 = NQ * 16 * 16;
        int t3 = NQ * 8 * 8;
        cpool_kernel<<<(t1 + 255) / 256, 256>>>(0, t1);
        cpool_kernel<<<(t2 + 255) / 256, 256>>>(1, t2);
        cpool_kernel<<<(t3 + 255) / 256, 256>>>(2, t3);
    }

    sample_kernel<<<NQ / QT, 256>>>(coords, out);
}

// round 6
// speedup vs baseline: 1.6650x; 1.2489x over previous
#include <cuda_runtime.h>
#include <cuda_fp16.h>
#include <cstdint>

// Problem constants
#define BB 2
#define CC 256
#define HH 64
#define WW 64
#define HWC (HH*WW)          // 4096
#define NQ (BB*HWC)          // 8192
#define NLVL 4
#define RAD 4
#define QT 16                // queries per sampler tile

// GEMM tiling: 128x128 tile, K pipelined in 4 chunks of 64
#define TM 128
#define TN 128
#define KC 64
#define STAGE_BYTES (TM*KC*2 + TN*KC*2)      // 32 KB per stage
#define GEMM_SMEM_BYTES (2*STAGE_BYTES + 1024)

// Scratch (device globals; allocation-free rule)
__device__ __half g_f1h[BB*HWC*CC];          // (B, HW, C) fp16, 4 MB
__device__ __half g_f2h[BB*HWC*CC];          // (B, HW, C) fp16, 4 MB
__device__ __half g_c0[(size_t)NQ*64*64];    // corr lvl0, 67 MB
__device__ __half g_c1[(size_t)NQ*32*32];    // 16.8 MB
__device__ __half g_c2[(size_t)NQ*16*16];    // 4.2 MB
__device__ __half g_c3[(size_t)NQ*8*8];      // 1.05 MB

__device__ __forceinline__ __half* clevel_ptr(int l) {
    switch (l) {
        case 0: return g_c0;
        case 1: return g_c1;
        case 2: return g_c2;
        default: return g_c3;
    }
}

__device__ __forceinline__ uint32_t smem_u32(const void* p) {
    uint32_t a;
    asm("{ .reg .u64 t; cvta.to.shared.u64 t, %1; cvt.u32.u64 %0, t; }"
        : "=r"(a) : "l"(p));
    return a;
}
__device__ __forceinline__ void cp16(uint32_t dst, const void* gsrc) {
    asm volatile("cp.async.cg.shared.global [%0], [%1], 16;"
                 :: "r"(dst), "l"(__cvta_generic_to_global(gsrc)) : "memory");
}
__device__ __forceinline__ void cp_commit() {
    asm volatile("cp.async.commit_group;" ::: "memory");
}
template <int N>
__device__ __forceinline__ void cp_wait() {
    asm volatile("cp.async.wait_group %0;" :: "n"(N) : "memory");
}

// ---------------------------------------------------------------------------
// Transpose (B,C,HW) fp32 -> (B,HW,C) fp16
// ---------------------------------------------------------------------------
__global__ void transpose_f1_kernel(const float* __restrict__ in) {
    __shared__ float tile[32][33];
    int b = blockIdx.z, hw0 = blockIdx.x*32, c0 = blockIdx.y*32;
    int tx = threadIdx.x, ty = threadIdx.y;
#pragma unroll
    for (int i = 0; i < 32; i += 8)
        tile[ty + i][tx] = in[(b*CC + c0 + ty + i) * HWC + hw0 + tx];
    __syncthreads();
#pragma unroll
    for (int i = 0; i < 32; i += 8)
        g_f1h[((size_t)b*HWC + hw0 + ty + i) * CC + c0 + tx] =
            __float2half_rn(tile[tx][ty + i]);
}
__global__ void transpose_f2_kernel(const float* __restrict__ in) {
    __shared__ float tile[32][33];
    int b = blockIdx.z, hw0 = blockIdx.x*32, c0 = blockIdx.y*32;
    int tx = threadIdx.x, ty = threadIdx.y;
#pragma unroll
    for (int i = 0; i < 32; i += 8)
        tile[ty + i][tx] = in[(b*CC + c0 + ty + i) * HWC + hw0 + tx];
    __syncthreads();
#pragma unroll
    for (int i = 0; i < 32; i += 8)
        g_f2h[((size_t)b*HWC + hw0 + ty + i) * CC + c0 + tx] =
            __float2half_rn(tile[tx][ty + i]);
}

// ---------------------------------------------------------------------------
// Pipelined GEMM via mma.sync: corr = f1 @ f2^T / 16 (fp16 out) + fused l1.
// 2-stage cp.async double buffer over 4 K-chunks of 64.
// Stage layout: rows of 64 halfs (128 B), chunks XOR-swizzled within row.
// ---------------------------------------------------------------------------
__global__ __launch_bounds__(256, 2)
void gemm_kernel() {
    extern __shared__ __align__(16) char dsm[];
    uint32_t raw = smem_u32(dsm);
    uint32_t sb  = (raw + 1023u) & ~1023u;
    char*    smp = dsm + (sb - raw);

    int tid = threadIdx.x;
    int lid = tid & 31;
    int w   = tid >> 5;
    int wm  = w & 3;                          // M group (4 x 32)
    int wn  = w >> 2;                         // N group (2 x 64)
    int b   = blockIdx.z;
    int i0  = blockIdx.y * TM;
    int j0  = blockIdx.x * TN;

    const uint4* gA = (const uint4*)(g_f1h + ((size_t)(b*HWC + i0)) * CC);
    const uint4* gB = (const uint4*)(g_f2h + ((size_t)(b*HWC + j0)) * CC);

    // issue loads for one stage: 1024 uint4 for A + 1024 for B (8/thread)
    auto load_stage = [&](int st, int kc) {
        uint32_t sS = sb + st * STAGE_BYTES;
#pragma unroll
        for (int i = 0; i < 4; i++) {
            int idx = tid + i * 256;          // 0..1023 (A)
            int r = idx >> 3, cl = idx & 7;
            uint32_t off = (uint32_t)r * 128u + (uint32_t)((cl ^ (r & 7)) << 4);
            cp16(sS + off, gA + r * 32 + kc * 8 + cl);
        }
#pragma unroll
        for (int i = 0; i < 4; i++) {
            int idx = tid + i * 256;          // 0..1023 (B)
            int r = idx >> 3, cl = idx & 7;
            uint32_t off = (uint32_t)r * 128u + (uint32_t)((cl ^ (r & 7)) << 4);
            cp16(sS + TM*KC*2 + off, gB + r * 32 + kc * 8 + cl);
        }
        cp_commit();
    };

    float acc[2][8][4];
#pragma unroll
    for (int mi = 0; mi < 2; mi++)
#pragma unroll
        for (int j = 0; j < 8; j++)
#pragma unroll
            for (int u = 0; u < 4; u++) acc[mi][j][u] = 0.f;

    int m0 = wm * 32;
    int nb = wn * 64;
    int arow = m0 + (lid & 15);
    int acb  = lid >> 4;
    int brow = nb + (lid & 7) + ((lid >> 4) << 3);
    int bcb  = (lid >> 3) & 1;

    load_stage(0, 0);

#pragma unroll
    for (int kc = 0; kc < 4; kc++) {
        if (kc < 3) load_stage((kc + 1) & 1, kc + 1);
        if (kc < 3) cp_wait<1>(); else cp_wait<0>();
        __syncthreads();

        uint32_t sA = sb + (kc & 1) * STAGE_BYTES;
        uint32_t sB = sA + TM*KC*2;
#pragma unroll
        for (int ks = 0; ks < 4; ks++) {
            uint32_t a[2][4];
#pragma unroll
            for (int mi = 0; mi < 2; mi++) {
                int row = arow + mi * 16;
                int ch  = ks * 2 + acb;
                uint32_t addr = sA + (uint32_t)row * 128u
                              + (uint32_t)((ch ^ (row & 7)) << 4);
                asm volatile(
                    "ldmatrix.sync.aligned.m8n8.x4.shared.b16 {%0,%1,%2,%3}, [%4];"
                    : "=r"(a[mi][0]), "=r"(a[mi][1]), "=r"(a[mi][2]), "=r"(a[mi][3])
                    : "r"(addr));
            }
            uint32_t bf[4][4];
#pragma unroll
            for (int ng = 0; ng < 4; ng++) {
                int row = brow + ng * 16;
                int ch  = ks * 2 + bcb;
                uint32_t addr = sB + (uint32_t)row * 128u
                              + (uint32_t)((ch ^ (row & 7)) << 4);
                asm volatile(
                    "ldmatrix.sync.aligned.m8n8.x4.shared.b16 {%0,%1,%2,%3}, [%4];"
                    : "=r"(bf[ng][0]), "=r"(bf[ng][1]), "=r"(bf[ng][2]), "=r"(bf[ng][3])
                    : "r"(addr));
            }
#pragma unroll
            for (int mi = 0; mi < 2; mi++)
#pragma unroll
                for (int j = 0; j < 8; j++) {
                    int ng = j >> 1, pr = (j & 1) * 2;
                    asm volatile(
                        "mma.sync.aligned.m16n8k16.row.col.f32.f16.f16.f32 "
                        "{%0,%1,%2,%3}, {%4,%5,%6,%7}, {%8,%9}, {%0,%1,%2,%3};"
                        : "+f"(acc[mi][j][0]), "+f"(acc[mi][j][1]),
                          "+f"(acc[mi][j][2]), "+f"(acc[mi][j][3])
                        : "r"(a[mi][0]), "r"(a[mi][1]), "r"(a[mi][2]), "r"(a[mi][3]),
                          "r"(bf[ng][pr]), "r"(bf[ng][pr + 1]));
                }
        }
        __syncthreads();
    }

    // ---- epilogue: fragments -> smem (fp16, 128x128) -> c0 + fused l1 ----
    {
        __half* epi = (__half*)smp;           // 32 KB, reuse stage 0
        const float s = 0.0625f;              // 1/sqrt(256)
#pragma unroll
        for (int mi = 0; mi < 2; mi++)
#pragma unroll
            for (int j = 0; j < 8; j++) {
                int n = nb + j * 8 + (lid & 3) * 2;
                int m = m0 + mi * 16 + (lid >> 2);
                *(__half2*)(epi + m * 128 + n) =
                    __floats2half2_rn(acc[mi][j][0] * s, acc[mi][j][1] * s);
                *(__half2*)(epi + (m + 8) * 128 + n) =
                    __floats2half2_rn(acc[mi][j][2] * s, acc[mi][j][3] * s);
            }
        __syncthreads();

        // c0 stores (coalesced 128B rows)
        const uint4* ev = (const uint4*)epi;
#pragma unroll
        for (int it = 0; it < 8; it++) {
            int idx = tid + it * 256;         // 2048 uint4
            int r = idx >> 4, c = idx & 15;
            *(uint4*)(g_c0 + ((size_t)(b*HWC + i0 + r)) * HWC + j0 + c * 8) =
                ev[idx];
        }

        // fused l1: this block's 128 columns = jy rows {2bx, 2bx+1} -> l1 row bx
        {
            int m   = tid >> 1;               // 0..127
            int seg = tid & 1;                // 16 jx1 each
            const __half* row = epi + m * 128;
            __half2 o[8];
#pragma unroll
            for (int u = 0; u < 8; u++) {
                int jx1a = seg * 16 + u * 2;
                float2 a0 = __half22float2(*(const __half2*)(row + 2*jx1a));
                float2 a1 = __half22float2(*(const __half2*)(row + 64 + 2*jx1a));
                float2 b0 = __half22float2(*(const __half2*)(row + 2*jx1a + 2));
                float2 b1 = __half22float2(*(const __half2*)(row + 64 + 2*jx1a + 2));
                o[u] = __floats2half2_rn(0.25f * (a0.x + a0.y + a1.x + a1.y),
                                         0.25f * (b0.x + b0.y + b1.x + b1.y));
            }
            __half* dst = g_c1 + ((size_t)(b*HWC + i0 + m)) * 1024
                        + blockIdx.x * 32 + seg * 16;
            ((uint4*)dst)[0] = ((uint4*)o)[0];
            ((uint4*)dst)[1] = ((uint4*)o)[1];
        }
    }
}

// ---------------------------------------------------------------------------
// Fused l1 -> l2 + l3: one thread per 4x4 l1 patch (= 2x2 l2 + 1 l3)
// ---------------------------------------------------------------------------
__global__ void cpool23_kernel() {
    int idx = blockIdx.x * blockDim.x + threadIdx.x;
    if (idx >= NQ * 64) return;
    int n  = idx >> 6;
    int t  = idx & 63;
    int y3 = t >> 3, x3 = t & 7;
    const __half* l1 = g_c1 + (size_t)n * 1024;

    float s2[2][2] = {{0.f, 0.f}, {0.f, 0.f}};
#pragma unroll
    for (int r = 0; r < 4; r++) {
        const __half* rp = l1 + (4*y3 + r) * 32 + 4*x3;
        float2 p0 = __half22float2(*(const __half2*)rp);
        float2 p1 = __half22float2(*(const __half2*)(rp + 2));
        s2[r >> 1][0] += p0.x + p0.y;
        s2[r >> 1][1] += p1.x + p1.y;
    }
    __half* l2 = g_c2 + (size_t)n * 256;
#pragma unroll
    for (int r = 0; r < 2; r++)
        *(__half2*)(l2 + (2*y3 + r) * 16 + 2*x3) =
            __floats2half2_rn(s2[r][0] * 0.25f, s2[r][1] * 0.25f);
    g_c3[(size_t)n * 64 + y3 * 8 + x3] =
        __float2half_rn((s2[0][0] + s2[0][1] + s2[1][0] + s2[1][1]) * 0.0625f);
}

// ---------------------------------------------------------------------------
// Sampler: 16 queries per block (256 threads). Stage 4-level 10x10 windows
// in shared, then 324 bilinear outputs per query, coalesced stores.
// ---------------------------------------------------------------------------
__global__ __launch_bounds__(256)
void sample_kernel(const float* __restrict__ coords,
                   float* __restrict__ out) {
    __shared__ float sW[QT * 400];       // [q][l*100 + ty*10 + tx]
    __shared__ float sX[QT], sY[QT];

    int bidx = blockIdx.x;               // 0..511
    int b    = bidx >> 8;
    int hw0  = (bidx & 255) * QT;
    int tid  = threadIdx.x;

    if (tid < QT) {
        sX[tid] = coords[(b*2 + 0) * HWC + hw0 + tid];
        sY[tid] = coords[(b*2 + 1) * HWC + hw0 + tid];
    }
    __syncthreads();

#pragma unroll
    for (int i = 0; i < 25; i++) {
        int idx = tid + i * 256;
        int q = idx / 400;
        int r = idx - q * 400;
        int l = r / 100;
        int t = r - l * 100;
        int Wl = 64 >> l;
        float scale = 1.0f / (float)(1 << l);
        float xc = sX[q] * scale, yc = sY[q] * scale;
        int bx = (int)floorf(xc) - RAD;
        int by = (int)floorf(yc) - RAD;
        int ix = bx + t % 10;
        int iy = by + t / 10;
        float v = 0.f;
        if (ix >= 0 && ix < Wl && iy >= 0 && iy < Wl) {
            const __half* cl = clevel_ptr(l);
            int n = b * HWC + hw0 + q;
            v = __half2float(cl[(size_t)n * Wl * Wl + iy * Wl + ix]);
        }
        sW[idx] = v;
    }
    __syncthreads();

#pragma unroll
    for (int i = 0; i < 21; i++) {
        int idx = tid + i * 256;
        if (idx < 324 * QT) {
            int k  = idx >> 4;           // 0..323
            int qq = idx & 15;
            int l  = k / 81;
            int kk = k - l * 81;
            int cx = kk / 9;             // x-offset index (ref adds dy-grid to x)
            int ry = kk - cx * 9;        // y-offset index
            float scale = 1.0f / (float)(1 << l);
            float xq = sX[qq] * scale;
            float yq = sY[qq] * scale;
            float fx = xq - floorf(xq);
            float fy = yq - floorf(yq);
            const float* W = sW + qq * 400 + l * 100;
            float v00 = W[ ry      * 10 + cx    ];
            float v01 = W[ ry      * 10 + cx + 1];
            float v10 = W[(ry + 1) * 10 + cx    ];
            float v11 = W[(ry + 1) * 10 + cx + 1];
            float v = (1.f - fy) * ((1.f - fx) * v00 + fx * v01)
                    +        fy  * ((1.f - fx) * v10 + fx * v11);
            out[((size_t)(b * 324 + k)) * HWC + hw0 + qq] = v;
        }
    }
}

// ---------------------------------------------------------------------------
extern "C" void kernel_launch(void* const* d_in, const int* in_sizes, int n_in,
                              void* d_out, int out_size) {
    const float* fmap1  = (const float*)d_in[0];
    const float* fmap2  = (const float*)d_in[1];
    const float* coords = (const float*)d_in[2];
    float* out = (float*)d_out;

    cudaFuncSetAttribute(gemm_kernel,
                         cudaFuncAttributeMaxDynamicSharedMemorySize,
                         GEMM_SMEM_BYTES);

    dim3 tgrid(HWC / 32, CC / 32, BB);
    dim3 tblk(32, 8);
    transpose_f1_kernel<<<tgrid, tblk>>>(fmap1);
    transpose_f2_kernel<<<tgrid, tblk>>>(fmap2);

    dim3 ggrid(HWC / TN, HWC / TM, BB);  // (32, 32, 2)
    gemm_kernel<<<ggrid, 256, GEMM_SMEM_BYTES>>>();

    cpool23_kernel<<<(NQ * 64 + 255) / 256, 256>>>();

    sample_kernel<<<NQ / QT, 256>>>(coords, out);
}

// round 7
// speedup vs baseline: 1.7786x; 1.0682x over previous
#include <cuda_runtime.h>
#include <cuda_fp16.h>
#include <cstdint>

// Problem constants
#define BB 2
#define CC 256
#define HH 64
#define WW 64
#define HWC (HH*WW)          // 4096
#define NQ (BB*HWC)          // 8192
#define NLVL 4
#define RAD 4
#define QT 16                // queries per sampler tile
#define WS 112               // per-query window stride (100 used, padded)

// GEMM tiling: 128x128 tile, K pipelined in 4 chunks of 64
#define TM 128
#define TN 128
#define KC 64
#define STAGE_BYTES (TM*KC*2 + TN*KC*2)      // 32 KB per stage
#define GEMM_SMEM_BYTES (2*STAGE_BYTES + 1024)

// Scratch (device globals; allocation-free rule)
__device__ __half g_f1h[BB*HWC*CC];          // (B, HW, C) fp16, 4 MB
__device__ __half g_f2h[BB*HWC*CC];          // (B, HW, C) fp16, 4 MB
__device__ __half g_c1[(size_t)NQ*32*32];    // corr lvl1 volume, 16.8 MB
__device__ __half g_w0[(size_t)NQ*WS];       // per-query 10x10 windows
__device__ __half g_w1[(size_t)NQ*WS];
__device__ __half g_w2[(size_t)NQ*WS];
__device__ __half g_w3[(size_t)NQ*WS];

__device__ __forceinline__ uint32_t smem_u32(const void* p) {
    uint32_t a;
    asm("{ .reg .u64 t; cvta.to.shared.u64 t, %1; cvt.u32.u64 %0, t; }"
        : "=r"(a) : "l"(p));
    return a;
}
__device__ __forceinline__ void cp16(uint32_t dst, const void* gsrc) {
    asm volatile("cp.async.cg.shared.global [%0], [%1], 16;"
                 :: "r"(dst), "l"(__cvta_generic_to_global(gsrc)) : "memory");
}
__device__ __forceinline__ void cp_commit() {
    asm volatile("cp.async.commit_group;" ::: "memory");
}
template <int N>
__device__ __forceinline__ void cp_wait() {
    asm volatile("cp.async.wait_group %0;" :: "n"(N) : "memory");
}

// ---------------------------------------------------------------------------
// Zero w0 (gemm only writes in-bounds taps)
// ---------------------------------------------------------------------------
__global__ void fill_w0_kernel() {
    int i = blockIdx.x * blockDim.x + threadIdx.x;   // NQ*WS/8 uint4
    if (i < NQ * WS / 8)
        ((uint4*)g_w0)[i] = make_uint4(0u, 0u, 0u, 0u);
}

// ---------------------------------------------------------------------------
// Transpose (B,C,HW) fp32 -> (B,HW,C) fp16
// ---------------------------------------------------------------------------
__global__ void transpose_f1_kernel(const float* __restrict__ in) {
    __shared__ float tile[32][33];
    int b = blockIdx.z, hw0 = blockIdx.x*32, c0 = blockIdx.y*32;
    int tx = threadIdx.x, ty = threadIdx.y;
#pragma unroll
    for (int i = 0; i < 32; i += 8)
        tile[ty + i][tx] = in[(b*CC + c0 + ty + i) * HWC + hw0 + tx];
    __syncthreads();
#pragma unroll
    for (int i = 0; i < 32; i += 8)
        g_f1h[((size_t)b*HWC + hw0 + ty + i) * CC + c0 + tx] =
            __float2half_rn(tile[tx][ty + i]);
}
__global__ void transpose_f2_kernel(const float* __restrict__ in) {
    __shared__ float tile[32][33];
    int b = blockIdx.z, hw0 = blockIdx.x*32, c0 = blockIdx.y*32;
    int tx = threadIdx.x, ty = threadIdx.y;
#pragma unroll
    for (int i = 0; i < 32; i += 8)
        tile[ty + i][tx] = in[(b*CC + c0 + ty + i) * HWC + hw0 + tx];
    __syncthreads();
#pragma unroll
    for (int i = 0; i < 32; i += 8)
        g_f2h[((size_t)b*HWC + hw0 + ty + i) * CC + c0 + tx] =
            __float2half_rn(tile[tx][ty + i]);
}

// ---------------------------------------------------------------------------
// Pipelined GEMM (mma.sync): corr tile in smem -> fused l1 + l0 window scatter.
// No full c0 volume is ever written.
// ---------------------------------------------------------------------------
__global__ __launch_bounds__(256, 2)
void gemm_kernel(const float* __restrict__ coords) {
    extern __shared__ __align__(16) char dsm[];
    uint32_t raw = smem_u32(dsm);
    uint32_t sb  = (raw + 1023u) & ~1023u;
    char*    smp = dsm + (sb - raw);

    int tid = threadIdx.x;
    int lid = tid & 31;
    int w   = tid >> 5;
    int wm  = w & 3;                          // M group (4 x 32)
    int wn  = w >> 2;                         // N group (2 x 64)
    int b   = blockIdx.z;
    int i0  = blockIdx.y * TM;
    int j0  = blockIdx.x * TN;

    const uint4* gA = (const uint4*)(g_f1h + ((size_t)(b*HWC + i0)) * CC);
    const uint4* gB = (const uint4*)(g_f2h + ((size_t)(b*HWC + j0)) * CC);

    auto load_stage = [&](int st, int kc) {
        uint32_t sS = sb + st * STAGE_BYTES;
#pragma unroll
        for (int i = 0; i < 4; i++) {
            int idx = tid + i * 256;
            int r = idx >> 3, cl = idx & 7;
            uint32_t off = (uint32_t)r * 128u + (uint32_t)((cl ^ (r & 7)) << 4);
            cp16(sS + off, gA + r * 32 + kc * 8 + cl);
        }
#pragma unroll
        for (int i = 0; i < 4; i++) {
            int idx = tid + i * 256;
            int r = idx >> 3, cl = idx & 7;
            uint32_t off = (uint32_t)r * 128u + (uint32_t)((cl ^ (r & 7)) << 4);
            cp16(sS + TM*KC*2 + off, gB + r * 32 + kc * 8 + cl);
        }
        cp_commit();
    };

    float acc[2][8][4];
#pragma unroll
    for (int mi = 0; mi < 2; mi++)
#pragma unroll
        for (int j = 0; j < 8; j++)
#pragma unroll
            for (int u = 0; u < 4; u++) acc[mi][j][u] = 0.f;

    int m0 = wm * 32;
    int nb = wn * 64;
    int arow = m0 + (lid & 15);
    int acb  = lid >> 4;
    int brow = nb + (lid & 7) + ((lid >> 4) << 3);
    int bcb  = (lid >> 3) & 1;

    load_stage(0, 0);

#pragma unroll
    for (int kc = 0; kc < 4; kc++) {
        if (kc < 3) load_stage((kc + 1) & 1, kc + 1);
        if (kc < 3) cp_wait<1>(); else cp_wait<0>();
        __syncthreads();

        uint32_t sA = sb + (kc & 1) * STAGE_BYTES;
        uint32_t sB = sA + TM*KC*2;
#pragma unroll
        for (int ks = 0; ks < 4; ks++) {
            uint32_t a[2][4];
#pragma unroll
            for (int mi = 0; mi < 2; mi++) {
                int row = arow + mi * 16;
                int ch  = ks * 2 + acb;
                uint32_t addr = sA + (uint32_t)row * 128u
                              + (uint32_t)((ch ^ (row & 7)) << 4);
                asm volatile(
                    "ldmatrix.sync.aligned.m8n8.x4.shared.b16 {%0,%1,%2,%3}, [%4];"
                    : "=r"(a[mi][0]), "=r"(a[mi][1]), "=r"(a[mi][2]), "=r"(a[mi][3])
                    : "r"(addr));
            }
            uint32_t bf[4][4];
#pragma unroll
            for (int ng = 0; ng < 4; ng++) {
                int row = brow + ng * 16;
                int ch  = ks * 2 + bcb;
                uint32_t addr = sB + (uint32_t)row * 128u
                              + (uint32_t)((ch ^ (row & 7)) << 4);
                asm volatile(
                    "ldmatrix.sync.aligned.m8n8.x4.shared.b16 {%0,%1,%2,%3}, [%4];"
                    : "=r"(bf[ng][0]), "=r"(bf[ng][1]), "=r"(bf[ng][2]), "=r"(bf[ng][3])
                    : "r"(addr));
            }
#pragma unroll
            for (int mi = 0; mi < 2; mi++)
#pragma unroll
                for (int j = 0; j < 8; j++) {
                    int ng = j >> 1, pr = (j & 1) * 2;
                    asm volatile(
                        "mma.sync.aligned.m16n8k16.row.col.f32.f16.f16.f32 "
                        "{%0,%1,%2,%3}, {%4,%5,%6,%7}, {%8,%9}, {%0,%1,%2,%3};"
                        : "+f"(acc[mi][j][0]), "+f"(acc[mi][j][1]),
                          "+f"(acc[mi][j][2]), "+f"(acc[mi][j][3])
                        : "r"(a[mi][0]), "r"(a[mi][1]), "r"(a[mi][2]), "r"(a[mi][3]),
                          "r"(bf[ng][pr]), "r"(bf[ng][pr + 1]));
                }
        }
        __syncthreads();
    }

    // ---- epilogue: fragments -> smem tile -> fused l1 + l0 window scatter ----
    {
        __half* epi = (__half*)smp;           // 32 KB, reuse stage 0
        const float s = 0.0625f;              // 1/sqrt(256)
#pragma unroll
        for (int mi = 0; mi < 2; mi++)
#pragma unroll
            for (int j = 0; j < 8; j++) {
                int n = nb + j * 8 + (lid & 3) * 2;
                int m = m0 + mi * 16 + (lid >> 2);
                *(__half2*)(epi + m * 128 + n) =
                    __floats2half2_rn(acc[mi][j][0] * s, acc[mi][j][1] * s);
                *(__half2*)(epi + (m + 8) * 128 + n) =
                    __floats2half2_rn(acc[mi][j][2] * s, acc[mi][j][3] * s);
            }
        __syncthreads();

        // fused l1: this block's 128 cols = jy rows {2bx,2bx+1} -> l1 row bx
        {
            int m   = tid >> 1;               // 0..127
            int seg = tid & 1;                // 16 x1 each
            const __half* row = epi + m * 128;
            __half2 o[8];
#pragma unroll
            for (int u = 0; u < 8; u++) {
                int x1 = seg * 16 + u * 2;
                float2 a0 = __half22float2(*(const __half2*)(row + 2*x1));
                float2 a1 = __half22float2(*(const __half2*)(row + 64 + 2*x1));
                float2 b0 = __half22float2(*(const __half2*)(row + 2*x1 + 2));
                float2 b1 = __half22float2(*(const __half2*)(row + 64 + 2*x1 + 2));
                o[u] = __floats2half2_rn(0.25f * (a0.x + a0.y + a1.x + a1.y),
                                         0.25f * (b0.x + b0.y + b1.x + b1.y));
            }
            __half* dst = g_c1 + ((size_t)(b*HWC + i0 + m)) * 1024
                        + blockIdx.x * 32 + seg * 16;
            ((uint4*)dst)[0] = ((uint4*)o)[0];
            ((uint4*)dst)[1] = ((uint4*)o)[1];
        }

        // l0 window scatter: 2 threads per query, one jy row each
        {
            int m    = tid >> 1;              // query row 0..127
            int half = tid & 1;
            int i    = i0 + m;
            float x = coords[(b*2 + 0) * HWC + i];
            float y = coords[(b*2 + 1) * HWC + i];
            int bx0 = (int)floorf(x) - RAD;
            int by0 = (int)floorf(y) - RAD;
            int jy  = 2 * blockIdx.x + half;
            int dy  = jy - by0;
            if (dy >= 0 && dy < 10) {
                const __half* row = epi + m * 128 + half * 64;
                __half* wq = g_w0 + (size_t)(b*HWC + i) * WS + dy * 10;
#pragma unroll
                for (int u = 0; u < 10; u++) {
                    int jx = bx0 + u;
                    if (jx >= 0 && jx < 64) wq[u] = row[jx];
                }
            }
        }
    }
}

// ---------------------------------------------------------------------------
// Warp-per-query: l1 (global) -> l2,l3 (smem) -> compact windows w1,w2,w3.
// ---------------------------------------------------------------------------
__global__ __launch_bounds__(256)
void pool_win_kernel(const float* __restrict__ coords) {
    __shared__ __half sl1[8][1024];
    __shared__ float  sl2[8][256];
    __shared__ float  sl3[8][64];

    int tid  = threadIdx.x;
    int q    = tid >> 5;
    int lane = tid & 31;
    int n    = blockIdx.x * 8 + q;

    // load l1[n] (2 KB)
    {
        const uint4* src = (const uint4*)(g_c1 + (size_t)n * 1024);
        uint4* d = (uint4*)sl1[q];
#pragma unroll
        for (int i = 0; i < 4; i++) d[lane + i*32] = src[lane + i*32];
    }
    __syncwarp();

    // l2: 256 cells, 8 per lane (fp32)
#pragma unroll
    for (int i = 0; i < 8; i++) {
        int c = lane + i*32;
        int y = c >> 4, x = c & 15;
        const __half* base = sl1[q] + (2*y)*32 + 2*x;
        float2 p0 = __half22float2(*(const __half2*)base);
        float2 p1 = __half22float2(*(const __half2*)(base + 32));
        sl2[q][c] = 0.25f * (p0.x + p0.y + p1.x + p1.y);
    }
    __syncwarp();

    // l3: 64 cells, 2 per lane
#pragma unroll
    for (int i = 0; i < 2; i++) {
        int c = lane + i*32;
        int y = c >> 3, x = c & 7;
        const float* base = sl2[q] + (2*y)*16 + 2*x;
        sl3[q][c] = 0.25f * (base[0] + base[1] + base[16] + base[17]);
    }
    __syncwarp();

    int b = n >> 12, hw = n & 4095;
    float xf = coords[(b*2 + 0) * HWC + hw];
    float yf = coords[(b*2 + 1) * HWC + hw];

#pragma unroll
    for (int l = 1; l < 4; l++) {
        int Wl = 64 >> l;
        float sc = 1.0f / (float)(1 << l);
        float xc = xf * sc, yc = yf * sc;
        int bx = (int)floorf(xc) - RAD;
        int by = (int)floorf(yc) - RAD;
        __half* wq = (l == 1 ? g_w1 : l == 2 ? g_w2 : g_w3) + (size_t)n * WS;
        for (int t = lane; t < 100; t += 32) {
            int ix = bx + t % 10;
            int iy = by + t / 10;
            float v = 0.f;
            if (ix >= 0 && ix < Wl && iy >= 0 && iy < Wl) {
                if      (l == 1) v = __half2float(sl1[q][iy*32 + ix]);
                else if (l == 2) v = sl2[q][iy*16 + ix];
                else             v = sl3[q][iy*8 + ix];
            }
            wq[t] = __float2half_rn(v);
        }
    }
}

// ---------------------------------------------------------------------------
// Sampler: 16 queries/block. Windows are compact & contiguous; stage to smem,
// then 324 bilinear outputs per query with lane->query coalesced stores.
// ---------------------------------------------------------------------------
__global__ __launch_bounds__(256)
void sample_kernel(const float* __restrict__ coords,
                   float* __restrict__ out) {
    __shared__ float sW[QT * 400];       // [q][l*100 + t]
    __shared__ float sX[QT], sY[QT];

    int bidx = blockIdx.x;               // 0..511
    int b    = bidx >> 8;
    int hw0  = (bidx & 255) * QT;
    int tid  = threadIdx.x;

    if (tid < QT) {
        sX[tid] = coords[(b*2 + 0) * HWC + hw0 + tid];
        sY[tid] = coords[(b*2 + 1) * HWC + hw0 + tid];
    }

    // stage 16 queries x 4 levels x 100 taps (contiguous reads)
#pragma unroll
    for (int i = 0; i < 25; i++) {
        int idx = tid + i * 256;
        int q = idx / 400;
        int r = idx - q * 400;
        int l = r / 100;
        int t = r - l * 100;
        const __half* wsrc =
            (l == 0 ? g_w0 : l == 1 ? g_w1 : l == 2 ? g_w2 : g_w3);
        sW[idx] = __half2float(wsrc[(size_t)(b*HWC + hw0 + q) * WS + t]);
    }
    __syncthreads();

#pragma unroll
    for (int i = 0; i < 21; i++) {
        int idx = tid + i * 256;
        if (idx < 324 * QT) {
            int k  = idx >> 4;           // 0..323
            int qq = idx & 15;
            int l  = k / 81;
            int kk = k - l * 81;
            int cx = kk / 9;             // x-offset index (ref adds dy-grid to x)
            int ry = kk - cx * 9;        // y-offset index
            float scale = 1.0f / (float)(1 << l);
            float xq = sX[qq] * scale;
            float yq = sY[qq] * scale;
            float fx = xq - floorf(xq);
            float fy = yq - floorf(yq);
            const float* W = sW + qq * 400 + l * 100;
            float v00 = W[ ry      * 10 + cx    ];
            float v01 = W[ ry      * 10 + cx + 1];
            float v10 = W[(ry + 1) * 10 + cx    ];
            float v11 = W[(ry + 1) * 10 + cx + 1];
            float v = (1.f - fy) * ((1.f - fx) * v00 + fx * v01)
                    +        fy  * ((1.f - fx) * v10 + fx * v11);
            out[((size_t)(b * 324 + k)) * HWC + hw0 + qq] = v;
        }
    }
}

// ---------------------------------------------------------------------------
extern "C" void kernel_launch(void* const* d_in, const int* in_sizes, int n_in,
                              void* d_out, int out_size) {
    const float* fmap1  = (const float*)d_in[0];
    const float* fmap2  = (const float*)d_in[1];
    const float* coords = (const float*)d_in[2];
    float* out = (float*)d_out;

    cudaFuncSetAttribute(gemm_kernel,
                         cudaFuncAttributeMaxDynamicSharedMemorySize,
                         GEMM_SMEM_BYTES);

    fill_w0_kernel<<<(NQ*WS/8 + 255) / 256, 256>>>();

    dim3 tgrid(HWC / 32, CC / 32, BB);
    dim3 tblk(32, 8);
    transpose_f1_kernel<<<tgrid, tblk>>>(fmap1);
    transpose_f2_kernel<<<tgrid, tblk>>>(fmap2);

    dim3 ggrid(HWC / TN, HWC / TM, BB);  // (32, 32, 2)
    gemm_kernel<<<ggrid, 256, GEMM_SMEM_BYTES>>>(coords);

    pool_win_kernel<<<NQ / 8, 256>>>(coords);

    sample_kernel<<<NQ / QT, 256>>>(coords, out);
}